// round 1
// baseline (speedup 1.0000x reference)
#include <cuda_runtime.h>
#include <cuda_bf16.h>
#include <cstddef>

// ---------------------------------------------------------------------------
// Problem constants (shapes fixed by setup_inputs)
// ---------------------------------------------------------------------------
#define BATCH   8
#define NPTS    1024
#define KNN     8
#define BN_ROWS (BATCH * NPTS)       // 8192
#define R_ROWS  (BN_ROWS * KNN)      // 65536
#define EPSBN   1e-5f

// ---------------------------------------------------------------------------
// Scratch (device globals: allocation-free)
// ---------------------------------------------------------------------------
__device__ float g_h0  [BN_ROWS * 64];
__device__ float g_feat[BN_ROWS * 256];
__device__ int   g_idx [R_ROWS];
__device__ float g_M   [2048 * 512];          // combined (WL | WR-WL) weights
__device__ float g_Y   [BN_ROWS * 2048];      // hoisted layer-1 outputs
__device__ float g_act [R_ROWS * 1024];       // layer-1 activations (post BN+ReLU)
__device__ float g_pre [R_ROWS * 1024];       // layer-2 pre-activations
__device__ float g_l0  [BN_ROWS * 512];
__device__ float g_stats[2 * 1024];           // per-channel sum / sumsq

// ---------------------------------------------------------------------------
// Tiny GEMM for K=3 (xyz @ W1^T)
// ---------------------------------------------------------------------------
__global__ void gemm_k3(const float* __restrict__ xyz, const float* __restrict__ W,
                        float* __restrict__ out) {
    int i = blockIdx.x * blockDim.x + threadIdx.x;
    if (i >= BN_ROWS * 64) return;
    int r = i >> 6, o = i & 63;
    const float* x = xyz + r * 3;
    const float* w = W + o * 3;
    out[i] = fmaf(x[0], w[0], fmaf(x[1], w[1], x[2] * w[2]));
}

// ---------------------------------------------------------------------------
// Tiled fp32 GEMM:  C[m,n] = sum_k A[m,k] * B[n,k]
// Requires M%128==0, N%128==0, K%16==0 (all shapes here satisfy this).
// ---------------------------------------------------------------------------
__global__ __launch_bounds__(256)
void gemm_tn(const float* __restrict__ A, const float* __restrict__ Bm,
             float* __restrict__ C, int M, int N, int K) {
    __shared__ float As[16][132];
    __shared__ float Bs[16][132];
    const int tid = threadIdx.x;
    const int bm = blockIdx.y * 128;
    const int bn = blockIdx.x * 128;
    const int tx = tid & 15, ty = tid >> 4;

    float acc[8][8];
#pragma unroll
    for (int i = 0; i < 8; i++)
#pragma unroll
        for (int j = 0; j < 8; j++) acc[i][j] = 0.f;

    const int lrow = tid >> 2;            // 0..63
    const int lk4  = (tid & 3) * 4;       // 0,4,8,12

    for (int k0 = 0; k0 < K; k0 += 16) {
#pragma unroll
        for (int h = 0; h < 2; h++) {
            int r = lrow + h * 64;
            float4 v = *(const float4*)&A [(size_t)(bm + r) * K + k0 + lk4];
            As[lk4 + 0][r] = v.x; As[lk4 + 1][r] = v.y;
            As[lk4 + 2][r] = v.z; As[lk4 + 3][r] = v.w;
            float4 w = *(const float4*)&Bm[(size_t)(bn + r) * K + k0 + lk4];
            Bs[lk4 + 0][r] = w.x; Bs[lk4 + 1][r] = w.y;
            Bs[lk4 + 2][r] = w.z; Bs[lk4 + 3][r] = w.w;
        }
        __syncthreads();
#pragma unroll
        for (int kk = 0; kk < 16; kk++) {
            float a[8], b[8];
#pragma unroll
            for (int i = 0; i < 8; i++) a[i] = As[kk][ty * 8 + i];
#pragma unroll
            for (int j = 0; j < 8; j++) b[j] = Bs[kk][tx * 8 + j];
#pragma unroll
            for (int i = 0; i < 8; i++)
#pragma unroll
                for (int j = 0; j < 8; j++)
                    acc[i][j] = fmaf(a[i], b[j], acc[i][j]);
        }
        __syncthreads();
    }
#pragma unroll
    for (int i = 0; i < 8; i++) {
        int m = bm + ty * 8 + i;
#pragma unroll
        for (int j = 0; j < 8; j += 4) {
            float4 v = make_float4(acc[i][j], acc[i][j+1], acc[i][j+2], acc[i][j+3]);
            *(float4*)&C[(size_t)m * N + bn + tx * 8 + j] = v;
        }
    }
}

// ---------------------------------------------------------------------------
// Brute-force kNN (per batch, all-pairs in SMEM). Matches top_k(-d2) tie rules.
// ---------------------------------------------------------------------------
__global__ __launch_bounds__(256)
void knn_kernel(const float* __restrict__ xyz, int* __restrict__ idx) {
    __shared__ float sx[NPTS], sy[NPTS], sz[NPTS], sq[NPTS];
    const int b = blockIdx.x;
    const float* p = xyz + (size_t)b * NPTS * 3;
    for (int m = threadIdx.x; m < NPTS; m += 256) {
        float x = p[m * 3], y = p[m * 3 + 1], z = p[m * 3 + 2];
        sx[m] = x; sy[m] = y; sz[m] = z;
        sq[m] = x * x + y * y + z * z;
    }
    __syncthreads();
    for (int n = threadIdx.x; n < NPTS; n += 256) {
        float qx = sx[n], qy = sy[n], qz = sz[n], qs = sq[n];
        float bd[KNN]; int bi[KNN];
#pragma unroll
        for (int j = 0; j < KNN; j++) { bd[j] = 3.4e38f; bi[j] = -1; }
        float worst = bd[KNN - 1];
        for (int m = 0; m < NPTS; m++) {
            float d = qs + sq[m] - 2.f * fmaf(qx, sx[m], fmaf(qy, sy[m], qz * sz[m]));
            if (d < worst) {               // strict < keeps earlier index on ties (stable)
                int j = KNN - 1;
                while (j > 0 && bd[j - 1] > d) { bd[j] = bd[j - 1]; bi[j] = bi[j - 1]; j--; }
                bd[j] = d; bi[j] = m;
                worst = bd[KNN - 1];
            }
        }
        for (int j = 0; j < KNN; j++) idx[((size_t)b * NPTS + n) * KNN + j] = bi[j];
    }
}

// ---------------------------------------------------------------------------
// Build combined weights: M[o]   = WL[o]  (= W[o, :Ci])
//                         M[O+o] = WR[o] - WL[o]
// so pre = M_top · feat[idx] + M_bot · feat[center]
// ---------------------------------------------------------------------------
__global__ void prepW(const float* __restrict__ W, float* __restrict__ Mo, int O, int Ci) {
    int i = blockIdx.x * blockDim.x + threadIdx.x;
    if (i >= O * Ci) return;
    int o = i / Ci, c = i - o * Ci;
    float wl = W[(size_t)o * 2 * Ci + c];
    float wr = W[(size_t)o * 2 * Ci + Ci + c];
    Mo[(size_t)o * Ci + c] = wl;
    Mo[(size_t)(O + o) * Ci + c] = wr - wl;
}

// out[row, c] = Y[gathered, c] + Y[center, C + c]   (row = ((b*N+n)*8+kk))
__global__ void gather_combine(const float* __restrict__ Y, const int* __restrict__ idx,
                               float* __restrict__ out, int C) {
    int row = blockIdx.x;
    int bn  = row >> 3;
    int b   = bn >> 10;
    int g   = idx[row];
    const float* yl = Y + (size_t)(b * NPTS + g) * (2 * C);
    const float* yc = Y + (size_t)bn * (2 * C) + C;
    float* o = out + (size_t)row * C;
    for (int c = threadIdx.x; c < C; c += blockDim.x)
        o[c] = yl[c] + yc[c];
}

// ---------------------------------------------------------------------------
// BN statistics (coalesced, split over rows; atomics into pre-zeroed stats)
// ---------------------------------------------------------------------------
__global__ void zero_kernel(float* p, int n) {
    int i = blockIdx.x * blockDim.x + threadIdx.x;
    if (i < n) p[i] = 0.f;
}

__global__ void col_stats(const float* __restrict__ x, float* __restrict__ stats,
                          int rows, int C) {
    int c = blockIdx.x * 256 + threadIdx.x;
    if (c >= C) return;
    int per = rows / gridDim.y;
    int r0 = blockIdx.y * per;
    float s = 0.f, s2 = 0.f;
    for (int r = r0; r < r0 + per; r++) {
        float v = x[(size_t)r * C + c];
        s += v;
        s2 = fmaf(v, v, s2);
    }
    atomicAdd(&stats[c], s);
    atomicAdd(&stats[C + c], s2);
}

// in-place BN + ReLU
__global__ void bn_relu_apply(float* __restrict__ x, const float* __restrict__ stats,
                              const float* __restrict__ g, const float* __restrict__ b,
                              int Cmask, int C, size_t total, float inv_n) {
    size_t i = (size_t)blockIdx.x * blockDim.x + threadIdx.x;
    if (i >= total) return;
    int c = (int)(i & Cmask);
    float mean = stats[c] * inv_n;
    float var  = fmaf(-mean, mean, stats[C + c] * inv_n);
    float rs   = rsqrtf(var + EPSBN);
    float v    = (x[i] - mean) * rs * g[c] + b[c];
    x[i] = v > 0.f ? v : 0.f;
}

// BN + affine, max over k, ReLU -> l0[bn, c]
__global__ void bn_relu_max(const float* __restrict__ pre, const float* __restrict__ stats,
                            const float* __restrict__ g, const float* __restrict__ bb,
                            float* __restrict__ out, int C, float inv_n) {
    int bn = blockIdx.x;
    for (int c = threadIdx.x; c < C; c += blockDim.x) {
        float mean = stats[c] * inv_n;
        float var  = fmaf(-mean, mean, stats[C + c] * inv_n);
        float rs   = rsqrtf(var + EPSBN);
        float gc   = g[c] * rs;
        float bc   = bb[c] - mean * gc;
        float m = -3.4e38f;
#pragma unroll
        for (int kk = 0; kk < KNN; kk++) {
            float v = fmaf(pre[((size_t)bn * KNN + kk) * C + c], gc, bc);
            m = fmaxf(m, v);
        }
        out[(size_t)bn * C + c] = m > 0.f ? m : 0.f;
    }
}

// same, but writes the final output transposed: out[b, c, n]
__global__ void bn_relu_max_T(const float* __restrict__ pre, const float* __restrict__ stats,
                              const float* __restrict__ g, const float* __restrict__ bb,
                              float* __restrict__ out, int C, float inv_n) {
    int bn = blockIdx.x;
    int b = bn >> 10, n = bn & 1023;
    for (int c = threadIdx.x; c < C; c += blockDim.x) {
        float mean = stats[c] * inv_n;
        float var  = fmaf(-mean, mean, stats[C + c] * inv_n);
        float rs   = rsqrtf(var + EPSBN);
        float gc   = g[c] * rs;
        float bc   = bb[c] - mean * gc;
        float m = -3.4e38f;
#pragma unroll
        for (int kk = 0; kk < KNN; kk++) {
            float v = fmaf(pre[((size_t)bn * KNN + kk) * C + c], gc, bc);
            m = fmaxf(m, v);
        }
        out[(size_t)b * C * NPTS + (size_t)c * NPTS + n] = m > 0.f ? m : 0.f;
    }
}

// ---------------------------------------------------------------------------
// Host orchestration
// ---------------------------------------------------------------------------
extern "C" void kernel_launch(void* const* d_in, const int* in_sizes, int n_in,
                              void* d_out, int out_size) {
    const float* xyz = (const float*)d_in[0];
    const float* W1  = (const float*)d_in[1];
    const float* g1  = (const float*)d_in[2];
    const float* b1  = (const float*)d_in[3];
    const float* W2  = (const float*)d_in[4];
    const float* g2  = (const float*)d_in[5];
    const float* b2  = (const float*)d_in[6];
    const float* WA1 = (const float*)d_in[7];
    const float* gA1 = (const float*)d_in[8];
    const float* bA1 = (const float*)d_in[9];
    const float* WA2 = (const float*)d_in[10];
    const float* gA2 = (const float*)d_in[11];
    const float* bA2 = (const float*)d_in[12];
    const float* WB1 = (const float*)d_in[13];
    const float* gB1 = (const float*)d_in[14];
    const float* bB1 = (const float*)d_in[15];
    const float* WB2 = (const float*)d_in[16];
    const float* gB2 = (const float*)d_in[17];
    const float* bB2 = (const float*)d_in[18];
    float* out = (float*)d_out;

    float *h0, *feat, *Mw, *Y, *act, *pre, *l0, *stats;
    int* idxp;
    cudaGetSymbolAddress((void**)&h0,    g_h0);
    cudaGetSymbolAddress((void**)&feat,  g_feat);
    cudaGetSymbolAddress((void**)&idxp,  g_idx);
    cudaGetSymbolAddress((void**)&Mw,    g_M);
    cudaGetSymbolAddress((void**)&Y,     g_Y);
    cudaGetSymbolAddress((void**)&act,   g_act);
    cudaGetSymbolAddress((void**)&pre,   g_pre);
    cudaGetSymbolAddress((void**)&l0,    g_l0);
    cudaGetSymbolAddress((void**)&stats, g_stats);

    const float invBN = 1.f / (float)BN_ROWS;   // 1/8192
    const float invR  = 1.f / (float)R_ROWS;    // 1/65536

    auto stats_pass = [&](const float* buf, int rows, int C) {
        zero_kernel<<<(2 * C + 255) / 256, 256>>>(stats, 2 * C);
        dim3 gs((C + 255) / 256, 64);
        col_stats<<<gs, 256>>>(buf, stats, rows, C);
    };

    // ---- stem MLP: xyz -> 64 -> 256 -----------------------------------
    gemm_k3<<<(BN_ROWS * 64 + 255) / 256, 256>>>(xyz, W1, h0);
    stats_pass(h0, BN_ROWS, 64);
    bn_relu_apply<<<(BN_ROWS * 64 + 255) / 256, 256>>>(h0, stats, g1, b1, 63, 64,
                                                       (size_t)BN_ROWS * 64, invBN);

    gemm_tn<<<dim3(256 / 128, BN_ROWS / 128), 256>>>(h0, W2, feat, BN_ROWS, 256, 64);
    stats_pass(feat, BN_ROWS, 256);
    bn_relu_apply<<<(BN_ROWS * 256 + 255) / 256, 256>>>(feat, stats, g2, b2, 255, 256,
                                                        (size_t)BN_ROWS * 256, invBN);

    // ---- kNN ----------------------------------------------------------
    knn_kernel<<<BATCH, 256>>>(xyz, idxp);

    // ---- stage A (512) ------------------------------------------------
    prepW<<<(512 * 256 + 255) / 256, 256>>>(WA1, Mw, 512, 256);
    gemm_tn<<<dim3(1024 / 128, BN_ROWS / 128), 256>>>(feat, Mw, Y, BN_ROWS, 1024, 256);
    gather_combine<<<R_ROWS, 256>>>(Y, idxp, act, 512);
    stats_pass(act, R_ROWS, 512);
    bn_relu_apply<<<(int)(((size_t)R_ROWS * 512 + 255) / 256), 256>>>(
        act, stats, gA1, bA1, 511, 512, (size_t)R_ROWS * 512, invR);

    gemm_tn<<<dim3(512 / 128, R_ROWS / 128), 256>>>(act, WA2, pre, R_ROWS, 512, 512);
    stats_pass(pre, R_ROWS, 512);
    bn_relu_max<<<BN_ROWS, 256>>>(pre, stats, gA2, bA2, l0, 512, invR);

    // ---- stage B (1024) -----------------------------------------------
    prepW<<<(1024 * 512 + 255) / 256, 256>>>(WB1, Mw, 1024, 512);
    gemm_tn<<<dim3(2048 / 128, BN_ROWS / 128), 256>>>(l0, Mw, Y, BN_ROWS, 2048, 512);
    gather_combine<<<R_ROWS, 256>>>(Y, idxp, act, 1024);
    stats_pass(act, R_ROWS, 1024);
    bn_relu_apply<<<(int)(((size_t)R_ROWS * 1024 + 255) / 256), 256>>>(
        act, stats, gB1, bB1, 1023, 1024, (size_t)R_ROWS * 1024, invR);

    gemm_tn<<<dim3(1024 / 128, R_ROWS / 128), 256>>>(act, WB2, pre, R_ROWS, 1024, 1024);
    stats_pass(pre, R_ROWS, 1024);
    bn_relu_max_T<<<BN_ROWS, 256>>>(pre, stats, gB2, bB2, out, 1024, invR);

    (void)in_sizes; (void)n_in; (void)out_size;
}

// round 3
// speedup vs baseline: 1.0833x; 1.0833x over previous
#include <cuda_runtime.h>
#include <cuda_bf16.h>
#include <cstddef>
#include <cstdint>

// ---------------------------------------------------------------------------
// Problem constants (shapes fixed by setup_inputs)
// ---------------------------------------------------------------------------
#define BATCH   8
#define NPTS    1024
#define KNN     8
#define BN_ROWS (BATCH * NPTS)       // 8192
#define R_ROWS  (BN_ROWS * KNN)      // 65536
#define EPSBN   1e-5f

// ---------------------------------------------------------------------------
// Scratch (device globals: allocation-free)
// ---------------------------------------------------------------------------
__device__ float g_h0  [BN_ROWS * 64];
__device__ float g_feat[BN_ROWS * 256];
__device__ int   g_idx [R_ROWS];
__device__ float g_M   [2048 * 512];          // combined (WL | WR-WL) weights
__device__ float g_Y   [BN_ROWS * 2048];      // hoisted layer-1 outputs
__device__ float g_act [R_ROWS * 1024];       // layer-1 pre-activations (raw)
__device__ float g_pre [R_ROWS * 1024];       // layer-2 pre-activations (raw)
__device__ float g_l0  [BN_ROWS * 512];
__device__ float g_stats[2 * 1024];           // per-channel sum / sumsq

// ---------------------------------------------------------------------------
// Packed f32x2 helpers (SASS FFMA2 — only reachable via PTX fma.rn.f32x2)
// ---------------------------------------------------------------------------
__device__ __forceinline__ unsigned long long pk2(float x) {
    unsigned long long r;
    asm("mov.b64 %0, {%1, %1};" : "=l"(r) : "r"(__float_as_uint(x)));
    return r;
}
__device__ __forceinline__ void fma2(unsigned long long& d,
                                     unsigned long long a, unsigned long long b) {
    asm("fma.rn.f32x2 %0, %1, %2, %0;" : "+l"(d) : "l"(a), "l"(b));
}

// ---------------------------------------------------------------------------
// Tiny GEMM for K=3 (xyz @ W1^T)
// ---------------------------------------------------------------------------
__global__ void gemm_k3(const float* __restrict__ xyz, const float* __restrict__ W,
                        float* __restrict__ out) {
    int i = blockIdx.x * blockDim.x + threadIdx.x;
    if (i >= BN_ROWS * 64) return;
    int r = i >> 6, o = i & 63;
    const float* x = xyz + r * 3;
    const float* w = W + o * 3;
    out[i] = fmaf(x[0], w[0], fmaf(x[1], w[1], x[2] * w[2]));
}

// ---------------------------------------------------------------------------
// Tiled fp32 GEMM with packed FFMA2 inner loop and optional fused BN+ReLU on
// the A operand:  C[m,n] = sum_k act(A[m,k]) * B[n,k]
//   act(v) = BN ? relu(v * gc[k] + bc[k]) : v
// Requires M%128==0, N%128==0, K%16==0, K<=1024.
// ---------------------------------------------------------------------------
template <bool DO_BN>
__global__ __launch_bounds__(256, 2)
void gemm_f2(const float* __restrict__ A, const float* __restrict__ Bm,
             float* __restrict__ C, int M, int N, int K,
             const float* __restrict__ stats, const float* __restrict__ gamma,
             const float* __restrict__ beta, float inv_n) {
    __shared__ float As[16][132];
    __shared__ float Bs[16][132];
    __shared__ float gcs[1024];
    __shared__ float bcs[1024];

    const int tid = threadIdx.x;
    const int bm = blockIdx.y * 128;
    const int bn = blockIdx.x * 128;
    const int tx = tid & 15, ty = tid >> 4;
    const int lrow = tid >> 2;            // 0..63
    const int lk4  = (tid & 3) * 4;       // 0,4,8,12

    if (DO_BN) {
        for (int k = tid; k < K; k += 256) {
            float mean = stats[k] * inv_n;
            float var  = fmaf(-mean, mean, stats[K + k] * inv_n);
            float rs   = rsqrtf(var + EPSBN);
            float gcv  = gamma[k] * rs;
            gcs[k] = gcv;
            bcs[k] = fmaf(-mean, gcv, beta[k]);
        }
        __syncthreads();
    }

    unsigned long long acc[8][4];
#pragma unroll
    for (int i = 0; i < 8; i++)
#pragma unroll
        for (int p = 0; p < 4; p++) acc[i][p] = 0ull;

    // register prefetch buffers (double-buffer the global loads)
    float4 va0, va1, vb0, vb1;
    {
        va0 = *(const float4*)&A [(size_t)(bm + lrow)      * K + lk4];
        va1 = *(const float4*)&A [(size_t)(bm + lrow + 64) * K + lk4];
        vb0 = *(const float4*)&Bm[(size_t)(bn + lrow)      * K + lk4];
        vb1 = *(const float4*)&Bm[(size_t)(bn + lrow + 64) * K + lk4];
    }

    for (int k0 = 0; k0 < K; k0 += 16) {
        // store current tile (with fused BN+ReLU on A)
        float4 a0 = va0, a1 = va1, b0 = vb0, b1 = vb1;
        if (DO_BN) {
            float g0 = gcs[k0 + lk4], g1v = gcs[k0 + lk4 + 1],
                  g2v = gcs[k0 + lk4 + 2], g3 = gcs[k0 + lk4 + 3];
            float c0 = bcs[k0 + lk4], c1 = bcs[k0 + lk4 + 1],
                  c2 = bcs[k0 + lk4 + 2], c3 = bcs[k0 + lk4 + 3];
            a0.x = fmaxf(fmaf(a0.x, g0, c0), 0.f);
            a0.y = fmaxf(fmaf(a0.y, g1v, c1), 0.f);
            a0.z = fmaxf(fmaf(a0.z, g2v, c2), 0.f);
            a0.w = fmaxf(fmaf(a0.w, g3, c3), 0.f);
            a1.x = fmaxf(fmaf(a1.x, g0, c0), 0.f);
            a1.y = fmaxf(fmaf(a1.y, g1v, c1), 0.f);
            a1.z = fmaxf(fmaf(a1.z, g2v, c2), 0.f);
            a1.w = fmaxf(fmaf(a1.w, g3, c3), 0.f);
        }
        As[lk4 + 0][lrow] = a0.x; As[lk4 + 1][lrow] = a0.y;
        As[lk4 + 2][lrow] = a0.z; As[lk4 + 3][lrow] = a0.w;
        As[lk4 + 0][lrow + 64] = a1.x; As[lk4 + 1][lrow + 64] = a1.y;
        As[lk4 + 2][lrow + 64] = a1.z; As[lk4 + 3][lrow + 64] = a1.w;
        Bs[lk4 + 0][lrow] = b0.x; Bs[lk4 + 1][lrow] = b0.y;
        Bs[lk4 + 2][lrow] = b0.z; Bs[lk4 + 3][lrow] = b0.w;
        Bs[lk4 + 0][lrow + 64] = b1.x; Bs[lk4 + 1][lrow + 64] = b1.y;
        Bs[lk4 + 2][lrow + 64] = b1.z; Bs[lk4 + 3][lrow + 64] = b1.w;
        __syncthreads();

        // prefetch next tile while computing
        if (k0 + 16 < K) {
            va0 = *(const float4*)&A [(size_t)(bm + lrow)      * K + k0 + 16 + lk4];
            va1 = *(const float4*)&A [(size_t)(bm + lrow + 64) * K + k0 + 16 + lk4];
            vb0 = *(const float4*)&Bm[(size_t)(bn + lrow)      * K + k0 + 16 + lk4];
            vb1 = *(const float4*)&Bm[(size_t)(bn + lrow + 64) * K + k0 + 16 + lk4];
        }

#pragma unroll
        for (int kk = 0; kk < 16; kk++) {
            unsigned long long bp0 = *(const unsigned long long*)&Bs[kk][tx * 8 + 0];
            unsigned long long bp1 = *(const unsigned long long*)&Bs[kk][tx * 8 + 2];
            unsigned long long bp2 = *(const unsigned long long*)&Bs[kk][tx * 8 + 4];
            unsigned long long bp3 = *(const unsigned long long*)&Bs[kk][tx * 8 + 6];
            float4 af0 = *(const float4*)&As[kk][ty * 8 + 0];
            float4 af1 = *(const float4*)&As[kk][ty * 8 + 4];
            float av[8] = {af0.x, af0.y, af0.z, af0.w, af1.x, af1.y, af1.z, af1.w};
#pragma unroll
            for (int i = 0; i < 8; i++) {
                unsigned long long ap = pk2(av[i]);
                fma2(acc[i][0], ap, bp0);
                fma2(acc[i][1], ap, bp1);
                fma2(acc[i][2], ap, bp2);
                fma2(acc[i][3], ap, bp3);
            }
        }
        __syncthreads();
    }

#pragma unroll
    for (int i = 0; i < 8; i++) {
        int m = bm + ty * 8 + i;
#pragma unroll
        for (int p = 0; p < 4; p += 2) {
            float4 v;
            v.x = __uint_as_float((unsigned)(acc[i][p]      & 0xffffffffull));
            v.y = __uint_as_float((unsigned)(acc[i][p]     >> 32));
            v.z = __uint_as_float((unsigned)(acc[i][p + 1]  & 0xffffffffull));
            v.w = __uint_as_float((unsigned)(acc[i][p + 1] >> 32));
            *(float4*)&C[(size_t)m * N + bn + tx * 8 + p * 2] = v;
        }
    }
}

// ---------------------------------------------------------------------------
// Brute-force kNN (per batch, all-pairs in SMEM). Matches top_k(-d2) tie rules.
// ---------------------------------------------------------------------------
__global__ __launch_bounds__(256)
void knn_kernel(const float* __restrict__ xyz, int* __restrict__ idx) {
    __shared__ float sx[NPTS], sy[NPTS], sz[NPTS], sq[NPTS];
    const int b = blockIdx.x;
    const float* p = xyz + (size_t)b * NPTS * 3;
    for (int m = threadIdx.x; m < NPTS; m += 256) {
        float x = p[m * 3], y = p[m * 3 + 1], z = p[m * 3 + 2];
        sx[m] = x; sy[m] = y; sz[m] = z;
        sq[m] = x * x + y * y + z * z;
    }
    __syncthreads();
    for (int n = threadIdx.x; n < NPTS; n += 256) {
        float qx = sx[n], qy = sy[n], qz = sz[n], qs = sq[n];
        float bd[KNN]; int bi[KNN];
#pragma unroll
        for (int j = 0; j < KNN; j++) { bd[j] = 3.4e38f; bi[j] = -1; }
        float worst = bd[KNN - 1];
        for (int m = 0; m < NPTS; m++) {
            float d = qs + sq[m] - 2.f * fmaf(qx, sx[m], fmaf(qy, sy[m], qz * sz[m]));
            if (d < worst) {               // strict < keeps earlier index on ties (stable)
                int j = KNN - 1;
                while (j > 0 && bd[j - 1] > d) { bd[j] = bd[j - 1]; bi[j] = bi[j - 1]; j--; }
                bd[j] = d; bi[j] = m;
                worst = bd[KNN - 1];
            }
        }
        for (int j = 0; j < KNN; j++) idx[((size_t)b * NPTS + n) * KNN + j] = bi[j];
    }
}

// ---------------------------------------------------------------------------
// Build combined weights: M[o] = WL[o];  M[O+o] = WR[o] - WL[o]
// ---------------------------------------------------------------------------
__global__ void prepW(const float* __restrict__ W, float* __restrict__ Mo, int O, int Ci) {
    int i = blockIdx.x * blockDim.x + threadIdx.x;
    if (i >= O * Ci) return;
    int o = i / Ci, c = i - o * Ci;
    float wl = W[(size_t)o * 2 * Ci + c];
    float wr = W[(size_t)o * 2 * Ci + Ci + c];
    Mo[(size_t)o * Ci + c] = wl;
    Mo[(size_t)(O + o) * Ci + c] = wr - wl;
}

// out[row, c] = Y[gathered, c] + Y[center, C + c]   (row = ((b*N+n)*8+kk))
__global__ void gather_combine(const float* __restrict__ Y, const int* __restrict__ idx,
                               float* __restrict__ out, int C) {
    int row = blockIdx.x;
    int bn  = row >> 3;
    int b   = bn >> 10;
    int g   = idx[row];
    const float* yl = Y + (size_t)(b * NPTS + g) * (2 * C);
    const float* yc = Y + (size_t)bn * (2 * C) + C;
    float* o = out + (size_t)row * C;
    for (int c = threadIdx.x; c < C; c += blockDim.x)
        o[c] = yl[c] + yc[c];
}

// ---------------------------------------------------------------------------
// BN statistics (coalesced, split over rows; atomics into pre-zeroed stats)
// ---------------------------------------------------------------------------
__global__ void zero_kernel(float* p, int n) {
    int i = blockIdx.x * blockDim.x + threadIdx.x;
    if (i < n) p[i] = 0.f;
}

__global__ void col_stats(const float* __restrict__ x, float* __restrict__ stats,
                          int rows, int C) {
    int c = blockIdx.x * 256 + threadIdx.x;
    if (c >= C) return;
    int per = rows / gridDim.y;
    int r0 = blockIdx.y * per;
    float s = 0.f, s2 = 0.f;
    for (int r = r0; r < r0 + per; r++) {
        float v = x[(size_t)r * C + c];
        s += v;
        s2 = fmaf(v, v, s2);
    }
    atomicAdd(&stats[c], s);
    atomicAdd(&stats[C + c], s2);
}

// BN + affine, max over k, ReLU -> out[bn, c]
__global__ void bn_relu_max(const float* __restrict__ pre, const float* __restrict__ stats,
                            const float* __restrict__ g, const float* __restrict__ bb,
                            float* __restrict__ out, int C, float inv_n) {
    int bn = blockIdx.x;
    for (int c = threadIdx.x; c < C; c += blockDim.x) {
        float mean = stats[c] * inv_n;
        float var  = fmaf(-mean, mean, stats[C + c] * inv_n);
        float rs   = rsqrtf(var + EPSBN);
        float gc   = g[c] * rs;
        float bc   = bb[c] - mean * gc;
        float m = -3.4e38f;
#pragma unroll
        for (int kk = 0; kk < KNN; kk++) {
            float v = fmaf(pre[((size_t)bn * KNN + kk) * C + c], gc, bc);
            m = fmaxf(m, v);
        }
        out[(size_t)bn * C + c] = m > 0.f ? m : 0.f;
    }
}

// same, but writes the final output transposed: out[b, c, n]
__global__ void bn_relu_max_T(const float* __restrict__ pre, const float* __restrict__ stats,
                              const float* __restrict__ g, const float* __restrict__ bb,
                              float* __restrict__ out, int C, float inv_n) {
    int bn = blockIdx.x;
    int b = bn >> 10, n = bn & 1023;
    for (int c = threadIdx.x; c < C; c += blockDim.x) {
        float mean = stats[c] * inv_n;
        float var  = fmaf(-mean, mean, stats[C + c] * inv_n);
        float rs   = rsqrtf(var + EPSBN);
        float gc   = g[c] * rs;
        float bc   = bb[c] - mean * gc;
        float m = -3.4e38f;
#pragma unroll
        for (int kk = 0; kk < KNN; kk++) {
            float v = fmaf(pre[((size_t)bn * KNN + kk) * C + c], gc, bc);
            m = fmaxf(m, v);
        }
        out[(size_t)b * C * NPTS + (size_t)c * NPTS + n] = m > 0.f ? m : 0.f;
    }
}

// ---------------------------------------------------------------------------
// Host orchestration
// ---------------------------------------------------------------------------
extern "C" void kernel_launch(void* const* d_in, const int* in_sizes, int n_in,
                              void* d_out, int out_size) {
    const float* xyz = (const float*)d_in[0];
    const float* W1  = (const float*)d_in[1];
    const float* g1  = (const float*)d_in[2];
    const float* b1  = (const float*)d_in[3];
    const float* W2  = (const float*)d_in[4];
    const float* g2  = (const float*)d_in[5];
    const float* b2  = (const float*)d_in[6];
    const float* WA1 = (const float*)d_in[7];
    const float* gA1 = (const float*)d_in[8];
    const float* bA1 = (const float*)d_in[9];
    const float* WA2 = (const float*)d_in[10];
    const float* gA2 = (const float*)d_in[11];
    const float* bA2 = (const float*)d_in[12];
    const float* WB1 = (const float*)d_in[13];
    const float* gB1 = (const float*)d_in[14];
    const float* bB1 = (const float*)d_in[15];
    const float* WB2 = (const float*)d_in[16];
    const float* gB2 = (const float*)d_in[17];
    const float* bB2 = (const float*)d_in[18];
    float* out = (float*)d_out;

    float *h0, *feat, *Mw, *Y, *act, *pre, *l0, *stats;
    int* idxp;
    cudaGetSymbolAddress((void**)&h0,    g_h0);
    cudaGetSymbolAddress((void**)&feat,  g_feat);
    cudaGetSymbolAddress((void**)&idxp,  g_idx);
    cudaGetSymbolAddress((void**)&Mw,    g_M);
    cudaGetSymbolAddress((void**)&Y,     g_Y);
    cudaGetSymbolAddress((void**)&act,   g_act);
    cudaGetSymbolAddress((void**)&pre,   g_pre);
    cudaGetSymbolAddress((void**)&l0,    g_l0);
    cudaGetSymbolAddress((void**)&stats, g_stats);

    const float invBN = 1.f / (float)BN_ROWS;   // 1/8192
    const float invR  = 1.f / (float)R_ROWS;    // 1/65536

    auto stats_pass = [&](const float* buf, int rows, int C) {
        zero_kernel<<<(2 * C + 255) / 256, 256>>>(stats, 2 * C);
        dim3 gs((C + 255) / 256, 64);
        col_stats<<<gs, 256>>>(buf, stats, rows, C);
    };

    // ---- stem MLP: xyz -> 64 (raw) -> stats -> fused-BN GEMM -> 256 (raw)
    gemm_k3<<<(BN_ROWS * 64 + 255) / 256, 256>>>(xyz, W1, h0);
    stats_pass(h0, BN_ROWS, 64);
    gemm_f2<true><<<dim3(256 / 128, BN_ROWS / 128), 256>>>(
        h0, W2, feat, BN_ROWS, 256, 64, stats, g1, b1, invBN);
    stats_pass(feat, BN_ROWS, 256);   // stats of feat (raw pre-activation)

    // ---- kNN ----------------------------------------------------------
    knn_kernel<<<BATCH, 256>>>(xyz, idxp);

    // ---- stage A (512) ------------------------------------------------
    prepW<<<(512 * 256 + 255) / 256, 256>>>(WA1, Mw, 512, 256);
    // Y = BN(feat) @ Mw^T   (fused BN on A with g2/b2)
    gemm_f2<true><<<dim3(1024 / 128, BN_ROWS / 128), 256>>>(
        feat, Mw, Y, BN_ROWS, 1024, 256, stats, g2, b2, invBN);
    gather_combine<<<R_ROWS, 256>>>(Y, idxp, act, 512);
    stats_pass(act, R_ROWS, 512);
    // pre = BN(act) @ WA2^T  (fused BN on A with gA1/bA1)
    gemm_f2<true><<<dim3(512 / 128, R_ROWS / 128), 256>>>(
        act, WA2, pre, R_ROWS, 512, 512, stats, gA1, bA1, invR);
    stats_pass(pre, R_ROWS, 512);
    bn_relu_max<<<BN_ROWS, 256>>>(pre, stats, gA2, bA2, l0, 512, invR);

    // ---- stage B (1024) -----------------------------------------------
    prepW<<<(1024 * 512 + 255) / 256, 256>>>(WB1, Mw, 1024, 512);
    gemm_f2<false><<<dim3(2048 / 128, BN_ROWS / 128), 256>>>(
        l0, Mw, Y, BN_ROWS, 2048, 512, nullptr, nullptr, nullptr, 0.f);
    gather_combine<<<R_ROWS, 256>>>(Y, idxp, act, 1024);
    stats_pass(act, R_ROWS, 1024);
    gemm_f2<true><<<dim3(1024 / 128, R_ROWS / 128), 256>>>(
        act, WB2, pre, R_ROWS, 1024, 1024, stats, gB1, bB1, invR);
    stats_pass(pre, R_ROWS, 1024);
    bn_relu_max_T<<<BN_ROWS, 256>>>(pre, stats, gB2, bB2, out, 1024, invR);

    (void)in_sizes; (void)n_in; (void)out_size;
}

// round 5
// speedup vs baseline: 1.5361x; 1.4180x over previous
#include <cuda_runtime.h>
#include <cuda_bf16.h>
#include <cstddef>
#include <cstdint>

// ---------------------------------------------------------------------------
// Problem constants
// ---------------------------------------------------------------------------
#define BATCH   8
#define NPTS    1024
#define KNN     8
#define BN_ROWS (BATCH * NPTS)       // 8192
#define R_ROWS  (BN_ROWS * KNN)      // 65536
#define EPSBN   1e-5f

// ---------------------------------------------------------------------------
// Scratch (device globals: allocation-free)
// ---------------------------------------------------------------------------
__device__ float g_h0  [BN_ROWS * 64];
__device__ float g_feat[BN_ROWS * 256];
__device__ int   g_idx [R_ROWS];
__device__ float g_Y   [BN_ROWS * 2048];
__device__ float g_act [R_ROWS * 1024];
__device__ float g_pre [R_ROWS * 1024];
__device__ float g_l0  [BN_ROWS * 512];
__device__ float g_stats[2 * 1024];
__device__ __nv_bfloat16 g_aH[R_ROWS * 1024];   // A operand hi plane
__device__ __nv_bfloat16 g_aL[R_ROWS * 1024];   // A operand lo plane
__device__ __nv_bfloat16 g_bH[2 * 1024 * 1024]; // B operand hi plane
__device__ __nv_bfloat16 g_bL[2 * 1024 * 1024]; // B operand lo plane

// ---------------------------------------------------------------------------
// PTX helpers (baseline ISA only — no 'a'-gated instructions)
// ---------------------------------------------------------------------------
__device__ __forceinline__ uint32_t smem_to_u32(const void* p) {
    uint32_t a;
    asm("{ .reg .u64 t; cvta.to.shared.u64 t, %1; cvt.u32.u64 %0, t; }" : "=r"(a) : "l"(p));
    return a;
}
#define CP16(d, s) \
    asm volatile("cp.async.cg.shared.global [%0], [%1], 16;" :: "r"(d), "l"(s))
#define CP_COMMIT() asm volatile("cp.async.commit_group;" ::: "memory")
#define CP_WAIT1()  asm volatile("cp.async.wait_group 1;" ::: "memory")

#define LDSM4(r, a) \
    asm volatile("ldmatrix.sync.aligned.m8n8.x4.shared.b16 {%0,%1,%2,%3}, [%4];" \
        : "=r"((r)[0]), "=r"((r)[1]), "=r"((r)[2]), "=r"((r)[3]) : "r"(a))

#define MMA16816(d, a, b) \
    asm volatile("mma.sync.aligned.m16n8k16.row.col.f32.bf16.bf16.f32 " \
        "{%0,%1,%2,%3}, {%4,%5,%6,%7}, {%8,%9}, {%0,%1,%2,%3};" \
        : "+f"((d)[0]), "+f"((d)[1]), "+f"((d)[2]), "+f"((d)[3]) \
        : "r"((a)[0]), "r"((a)[1]), "r"((a)[2]), "r"((a)[3]), \
          "r"((b)[0]), "r"((b)[1]))

// ---------------------------------------------------------------------------
// bf16-split tensor-core GEMM:  C[m,n] = sum_k A[m,k]*B[n,k]  (fp32-accurate)
// A = aH+aL, B = bH+bL.  acc += AhBh + AhBl + AlBh  (fp32 accumulators).
// CTA tile 128x128, 8 warps (2x4) of 64x32, K chunk 16, cp.async double buffer.
// SMEM row stride 48B (3x16B) -> conflict-free ldmatrix.
// grid = (N/128, M/128), block = 256, dyn smem = 49152.
// ---------------------------------------------------------------------------
#define GS  49152
#define BOF 24576u   // B planes offset in smem

__global__ __launch_bounds__(256, 1)
void gemm_mma(const __nv_bfloat16* __restrict__ aH, const __nv_bfloat16* __restrict__ aL,
              const __nv_bfloat16* __restrict__ bH, const __nv_bfloat16* __restrict__ bL,
              float* __restrict__ C, int M, int N, int K) {
    extern __shared__ char sm[];
    const uint32_t sb = smem_to_u32(sm);
    const int tid  = threadIdx.x;
    const int lane = tid & 31;
    const int wid  = tid >> 5;
    const int wm   = wid >> 2;          // 0..1
    const int wn   = wid & 3;           // 0..3
    const int bm = blockIdx.y * 128;
    const int bn = blockIdx.x * 128;

    // staging role: each thread copies one 16B chunk of each of the 4 planes
    const int r = tid >> 1;             // 0..127  (row)
    const int c = tid & 1;              // 0..1    (16B chunk within 32B k-row)

    auto stage = [&](int buf, int k0) {
        const char* a0 = (const char*)(aH + (size_t)(bm + r) * K + k0 + c * 8);
        const char* a1 = (const char*)(aL + (size_t)(bm + r) * K + k0 + c * 8);
        const char* b0 = (const char*)(bH + (size_t)(bn + r) * K + k0 + c * 8);
        const char* b1 = (const char*)(bL + (size_t)(bn + r) * K + k0 + c * 8);
        uint32_t dA0 = sb +        ((buf * 2 + 0) * 128 + r) * 48 + c * 16;
        uint32_t dA1 = sb +        ((buf * 2 + 1) * 128 + r) * 48 + c * 16;
        uint32_t dB0 = sb + BOF +  ((buf * 2 + 0) * 128 + r) * 48 + c * 16;
        uint32_t dB1 = sb + BOF +  ((buf * 2 + 1) * 128 + r) * 48 + c * 16;
        CP16(dA0, a0); CP16(dA1, a1); CP16(dB0, b0); CP16(dB1, b1);
        CP_COMMIT();
    };

    float acc[4][4][4];
#pragma unroll
    for (int mt = 0; mt < 4; mt++)
#pragma unroll
        for (int nt = 0; nt < 4; nt++)
#pragma unroll
            for (int e = 0; e < 4; e++) acc[mt][nt][e] = 0.f;

    const int nk = K >> 4;
    stage(0, 0);

    // precomputed ldmatrix lane addressing
    const int aRow = (lane & 15);
    const int aCol = (lane >> 4) * 16;
    const int bRow = (lane & 7) + ((lane >> 4) & 1) * 8;
    const int bCol = ((lane >> 3) & 1) * 16;

    for (int kt = 0; kt < nk; kt++) {
        if (kt + 1 < nk) stage((kt + 1) & 1, (kt + 1) << 4);
        else CP_COMMIT();               // empty group keeps wait count aligned
        CP_WAIT1();
        __syncthreads();

        const int buf = kt & 1;
        const uint32_t aB = sb +       (buf * 2) * 128 * 48;
        const uint32_t bB = sb + BOF + (buf * 2) * 128 * 48;

        uint32_t aFrag[2][4][4];
        uint32_t bFrag[2][4][2];
#pragma unroll
        for (int p = 0; p < 2; p++) {
#pragma unroll
            for (int mt = 0; mt < 4; mt++) {
                int row = wm * 64 + mt * 16 + aRow;
                LDSM4(aFrag[p][mt], aB + (uint32_t)(p * 128 + row) * 48 + aCol);
            }
#pragma unroll
            for (int nt2 = 0; nt2 < 2; nt2++) {
                int row = wn * 32 + nt2 * 16 + bRow;
                uint32_t t[4];
                LDSM4(t, bB + (uint32_t)(p * 128 + row) * 48 + bCol);
                bFrag[p][nt2 * 2 + 0][0] = t[0]; bFrag[p][nt2 * 2 + 0][1] = t[1];
                bFrag[p][nt2 * 2 + 1][0] = t[2]; bFrag[p][nt2 * 2 + 1][1] = t[3];
            }
        }
#pragma unroll
        for (int mt = 0; mt < 4; mt++)
#pragma unroll
            for (int nt = 0; nt < 4; nt++) {
                MMA16816(acc[mt][nt], aFrag[0][mt], bFrag[0][nt]);  // Ah*Bh
                MMA16816(acc[mt][nt], aFrag[0][mt], bFrag[1][nt]);  // Ah*Bl
                MMA16816(acc[mt][nt], aFrag[1][mt], bFrag[0][nt]);  // Al*Bh
            }
        __syncthreads();
    }

    // epilogue
#pragma unroll
    for (int mt = 0; mt < 4; mt++) {
        int m0 = bm + wm * 64 + mt * 16 + (lane >> 2);
#pragma unroll
        for (int nt = 0; nt < 4; nt++) {
            int n0 = bn + wn * 32 + nt * 8 + (lane & 3) * 2;
            *(float2*)&C[(size_t)m0 * N + n0] =
                make_float2(acc[mt][nt][0], acc[mt][nt][1]);
            *(float2*)&C[(size_t)(m0 + 8) * N + n0] =
                make_float2(acc[mt][nt][2], acc[mt][nt][3]);
        }
    }
}

// ---------------------------------------------------------------------------
// Tiny GEMM for K=3
// ---------------------------------------------------------------------------
__global__ void gemm_k3(const float* __restrict__ xyz, const float* __restrict__ W,
                        float* __restrict__ out) {
    int i = blockIdx.x * blockDim.x + threadIdx.x;
    if (i >= BN_ROWS * 64) return;
    int r = i >> 6, o = i & 63;
    const float* x = xyz + r * 3;
    const float* w = W + o * 3;
    out[i] = fmaf(x[0], w[0], fmaf(x[1], w[1], x[2] * w[2]));
}

// ---------------------------------------------------------------------------
// Split fp32 -> bf16 hi/lo planes, optional fused BN+ReLU (4-wide)
// ---------------------------------------------------------------------------
template <bool DO_BN>
__global__ void split_kernel(const float4* __restrict__ x, uint2* __restrict__ hi,
                             uint2* __restrict__ lo, const float* __restrict__ stats,
                             const float* __restrict__ g, const float* __restrict__ b,
                             int Cmask4, int C, size_t total4, float inv_n) {
    size_t i = (size_t)blockIdx.x * blockDim.x + threadIdx.x;
    if (i >= total4) return;
    float4 v = x[i];
    float vv[4] = {v.x, v.y, v.z, v.w};
    if (DO_BN) {
        int c = (int)((i & (size_t)Cmask4) << 2);
#pragma unroll
        for (int j = 0; j < 4; j++) {
            float mean = stats[c + j] * inv_n;
            float var  = fmaf(-mean, mean, stats[C + c + j] * inv_n);
            float rs   = rsqrtf(var + EPSBN);
            float gc   = g[c + j] * rs;
            float bc   = fmaf(-mean, gc, b[c + j]);
            vv[j] = fmaxf(fmaf(vv[j], gc, bc), 0.f);
        }
    }
    __nv_bfloat16 h[4], l[4];
#pragma unroll
    for (int j = 0; j < 4; j++) {
        h[j] = __float2bfloat16(vv[j]);
        l[j] = __float2bfloat16(vv[j] - __bfloat162float(h[j]));
    }
    __nv_bfloat162 h01 = __halves2bfloat162(h[0], h[1]);
    __nv_bfloat162 h23 = __halves2bfloat162(h[2], h[3]);
    __nv_bfloat162 l01 = __halves2bfloat162(l[0], l[1]);
    __nv_bfloat162 l23 = __halves2bfloat162(l[2], l[3]);
    uint2 uh, ul;
    uh.x = *(uint32_t*)&h01; uh.y = *(uint32_t*)&h23;
    ul.x = *(uint32_t*)&l01; ul.y = *(uint32_t*)&l23;
    hi[i] = uh; lo[i] = ul;
}

// plain weight split
__global__ void convW_split(const float* __restrict__ W, __nv_bfloat16* __restrict__ hi,
                            __nv_bfloat16* __restrict__ lo, int n) {
    int i = blockIdx.x * blockDim.x + threadIdx.x;
    if (i >= n) return;
    float v = W[i];
    __nv_bfloat16 h = __float2bfloat16(v);
    hi[i] = h;
    lo[i] = __float2bfloat16(v - __bfloat162float(h));
}

// combined weights split: row o = WL[o], row O+o = WR[o]-WL[o]
__global__ void prepW_split(const float* __restrict__ W, __nv_bfloat16* __restrict__ hi,
                            __nv_bfloat16* __restrict__ lo, int O, int Ci) {
    int i = blockIdx.x * blockDim.x + threadIdx.x;
    if (i >= O * Ci) return;
    int o = i / Ci, c = i - o * Ci;
    float wl = W[(size_t)o * 2 * Ci + c];
    float wr = W[(size_t)o * 2 * Ci + Ci + c];
    __nv_bfloat16 h0 = __float2bfloat16(wl);
    __nv_bfloat16 h1 = __float2bfloat16(wr - wl);
    hi[(size_t)o * Ci + c] = h0;
    lo[(size_t)o * Ci + c] = __float2bfloat16(wl - __bfloat162float(h0));
    hi[(size_t)(O + o) * Ci + c] = h1;
    lo[(size_t)(O + o) * Ci + c] = __float2bfloat16((wr - wl) - __bfloat162float(h1));
}

// ---------------------------------------------------------------------------
// kNN (verified)
// ---------------------------------------------------------------------------
__global__ __launch_bounds__(256)
void knn_kernel(const float* __restrict__ xyz, int* __restrict__ idx) {
    __shared__ float sx[NPTS], sy[NPTS], sz[NPTS], sq[NPTS];
    const int b = blockIdx.x;
    const float* p = xyz + (size_t)b * NPTS * 3;
    for (int m = threadIdx.x; m < NPTS; m += 256) {
        float x = p[m * 3], y = p[m * 3 + 1], z = p[m * 3 + 2];
        sx[m] = x; sy[m] = y; sz[m] = z;
        sq[m] = x * x + y * y + z * z;
    }
    __syncthreads();
    for (int n = threadIdx.x; n < NPTS; n += 256) {
        float qx = sx[n], qy = sy[n], qz = sz[n], qs = sq[n];
        float bd[KNN]; int bi[KNN];
#pragma unroll
        for (int j = 0; j < KNN; j++) { bd[j] = 3.4e38f; bi[j] = -1; }
        float worst = bd[KNN - 1];
        for (int m = 0; m < NPTS; m++) {
            float d = qs + sq[m] - 2.f * fmaf(qx, sx[m], fmaf(qy, sy[m], qz * sz[m]));
            if (d < worst) {
                int j = KNN - 1;
                while (j > 0 && bd[j - 1] > d) { bd[j] = bd[j - 1]; bi[j] = bi[j - 1]; j--; }
                bd[j] = d; bi[j] = m;
                worst = bd[KNN - 1];
            }
        }
        for (int j = 0; j < KNN; j++) idx[((size_t)b * NPTS + n) * KNN + j] = bi[j];
    }
}

// out[row, c] = Y[gathered, c] + Y[center, C + c]
__global__ void gather_combine(const float* __restrict__ Y, const int* __restrict__ idx,
                               float* __restrict__ out, int C) {
    int row = blockIdx.x;
    int bn  = row >> 3;
    int b   = bn >> 10;
    int g   = idx[row];
    const float* yl = Y + (size_t)(b * NPTS + g) * (2 * C);
    const float* yc = Y + (size_t)bn * (2 * C) + C;
    float* o = out + (size_t)row * C;
    for (int c = threadIdx.x; c < C; c += blockDim.x)
        o[c] = yl[c] + yc[c];
}

// ---------------------------------------------------------------------------
// BN statistics
// ---------------------------------------------------------------------------
__global__ void zero_kernel(float* p, int n) {
    int i = blockIdx.x * blockDim.x + threadIdx.x;
    if (i < n) p[i] = 0.f;
}

__global__ void col_stats(const float* __restrict__ x, float* __restrict__ stats,
                          int rows, int C) {
    int c = blockIdx.x * 256 + threadIdx.x;
    if (c >= C) return;
    int per = rows / gridDim.y;
    int r0 = blockIdx.y * per;
    float s = 0.f, s2 = 0.f;
    for (int r = r0; r < r0 + per; r++) {
        float v = x[(size_t)r * C + c];
        s += v;
        s2 = fmaf(v, v, s2);
    }
    atomicAdd(&stats[c], s);
    atomicAdd(&stats[C + c], s2);
}

// BN + affine, max over k, ReLU
__global__ void bn_relu_max(const float* __restrict__ pre, const float* __restrict__ stats,
                            const float* __restrict__ g, const float* __restrict__ bb,
                            float* __restrict__ out, int C, float inv_n) {
    int bn = blockIdx.x;
    for (int c = threadIdx.x; c < C; c += blockDim.x) {
        float mean = stats[c] * inv_n;
        float var  = fmaf(-mean, mean, stats[C + c] * inv_n);
        float rs   = rsqrtf(var + EPSBN);
        float gc   = g[c] * rs;
        float bc   = bb[c] - mean * gc;
        float m = -3.4e38f;
#pragma unroll
        for (int kk = 0; kk < KNN; kk++) {
            float v = fmaf(pre[((size_t)bn * KNN + kk) * C + c], gc, bc);
            m = fmaxf(m, v);
        }
        out[(size_t)bn * C + c] = m > 0.f ? m : 0.f;
    }
}

__global__ void bn_relu_max_T(const float* __restrict__ pre, const float* __restrict__ stats,
                              const float* __restrict__ g, const float* __restrict__ bb,
                              float* __restrict__ out, int C, float inv_n) {
    int bn = blockIdx.x;
    int b = bn >> 10, n = bn & 1023;
    for (int c = threadIdx.x; c < C; c += blockDim.x) {
        float mean = stats[c] * inv_n;
        float var  = fmaf(-mean, mean, stats[C + c] * inv_n);
        float rs   = rsqrtf(var + EPSBN);
        float gc   = g[c] * rs;
        float bc   = bb[c] - mean * gc;
        float m = -3.4e38f;
#pragma unroll
        for (int kk = 0; kk < KNN; kk++) {
            float v = fmaf(pre[((size_t)bn * KNN + kk) * C + c], gc, bc);
            m = fmaxf(m, v);
        }
        out[(size_t)b * C * NPTS + (size_t)c * NPTS + n] = m > 0.f ? m : 0.f;
    }
}

// ---------------------------------------------------------------------------
// Host orchestration
// ---------------------------------------------------------------------------
extern "C" void kernel_launch(void* const* d_in, const int* in_sizes, int n_in,
                              void* d_out, int out_size) {
    const float* xyz = (const float*)d_in[0];
    const float* W1  = (const float*)d_in[1];
    const float* g1  = (const float*)d_in[2];
    const float* b1  = (const float*)d_in[3];
    const float* W2  = (const float*)d_in[4];
    const float* g2  = (const float*)d_in[5];
    const float* b2  = (const float*)d_in[6];
    const float* WA1 = (const float*)d_in[7];
    const float* gA1 = (const float*)d_in[8];
    const float* bA1 = (const float*)d_in[9];
    const float* WA2 = (const float*)d_in[10];
    const float* gA2 = (const float*)d_in[11];
    const float* bA2 = (const float*)d_in[12];
    const float* WB1 = (const float*)d_in[13];
    const float* gB1 = (const float*)d_in[14];
    const float* bB1 = (const float*)d_in[15];
    const float* WB2 = (const float*)d_in[16];
    const float* gB2 = (const float*)d_in[17];
    const float* bB2 = (const float*)d_in[18];
    float* out = (float*)d_out;

    cudaFuncSetAttribute(gemm_mma, cudaFuncAttributeMaxDynamicSharedMemorySize, GS);

    float *h0, *feat, *Y, *act, *pre, *l0, *stats;
    int* idxp;
    __nv_bfloat16 *aH, *aL, *bH, *bL;
    cudaGetSymbolAddress((void**)&h0,    g_h0);
    cudaGetSymbolAddress((void**)&feat,  g_feat);
    cudaGetSymbolAddress((void**)&idxp,  g_idx);
    cudaGetSymbolAddress((void**)&Y,     g_Y);
    cudaGetSymbolAddress((void**)&act,   g_act);
    cudaGetSymbolAddress((void**)&pre,   g_pre);
    cudaGetSymbolAddress((void**)&l0,    g_l0);
    cudaGetSymbolAddress((void**)&stats, g_stats);
    cudaGetSymbolAddress((void**)&aH,    g_aH);
    cudaGetSymbolAddress((void**)&aL,    g_aL);
    cudaGetSymbolAddress((void**)&bH,    g_bH);
    cudaGetSymbolAddress((void**)&bL,    g_bL);

    const float invBN = 1.f / (float)BN_ROWS;
    const float invR  = 1.f / (float)R_ROWS;

    auto stats_pass = [&](const float* buf, int rows, int C) {
        zero_kernel<<<(2 * C + 255) / 256, 256>>>(stats, 2 * C);
        dim3 gs((C + 255) / 256, 64);
        col_stats<<<gs, 256>>>(buf, stats, rows, C);
    };
    auto split_bn = [&](const float* src, int rows, int C, const float* g, const float* b,
                        float inv_n) {
        size_t t4 = (size_t)rows * C / 4;
        split_kernel<true><<<(int)((t4 + 255) / 256), 256>>>(
            (const float4*)src, (uint2*)aH, (uint2*)aL, stats, g, b, C / 4 - 1, C, t4, inv_n);
    };
    auto split_plain = [&](const float* src, int rows, int C) {
        size_t t4 = (size_t)rows * C / 4;
        split_kernel<false><<<(int)((t4 + 255) / 256), 256>>>(
            (const float4*)src, (uint2*)aH, (uint2*)aL, nullptr, nullptr, nullptr,
            C / 4 - 1, C, t4, 0.f);
    };
    auto tc = [&](float* Cout, int M, int N, int K) {
        gemm_mma<<<dim3(N / 128, M / 128), 256, GS>>>(aH, aL, bH, bL, Cout, M, N, K);
    };

    // ---- stem: xyz -> 64 -> 256 ---------------------------------------
    gemm_k3<<<(BN_ROWS * 64 + 255) / 256, 256>>>(xyz, W1, h0);
    stats_pass(h0, BN_ROWS, 64);
    split_bn(h0, BN_ROWS, 64, g1, b1, invBN);
    convW_split<<<(256 * 64 + 255) / 256, 256>>>(W2, bH, bL, 256 * 64);
    tc(feat, BN_ROWS, 256, 64);
    stats_pass(feat, BN_ROWS, 256);

    // ---- kNN ----------------------------------------------------------
    knn_kernel<<<BATCH, 256>>>(xyz, idxp);

    // ---- stage A (512) ------------------------------------------------
    prepW_split<<<(512 * 256 + 255) / 256, 256>>>(WA1, bH, bL, 512, 256);
    split_bn(feat, BN_ROWS, 256, g2, b2, invBN);
    tc(Y, BN_ROWS, 1024, 256);
    gather_combine<<<R_ROWS, 256>>>(Y, idxp, act, 512);
    stats_pass(act, R_ROWS, 512);
    split_bn(act, R_ROWS, 512, gA1, bA1, invR);
    convW_split<<<(512 * 512 + 255) / 256, 256>>>(WA2, bH, bL, 512 * 512);
    tc(pre, R_ROWS, 512, 512);
    stats_pass(pre, R_ROWS, 512);
    bn_relu_max<<<BN_ROWS, 256>>>(pre, stats, gA2, bA2, l0, 512, invR);

    // ---- stage B (1024) -----------------------------------------------
    prepW_split<<<(1024 * 512 + 255) / 256, 256>>>(WB1, bH, bL, 1024, 512);
    split_plain(l0, BN_ROWS, 512);
    tc(Y, BN_ROWS, 2048, 512);
    gather_combine<<<R_ROWS, 256>>>(Y, idxp, act, 1024);
    stats_pass(act, R_ROWS, 1024);
    split_bn(act, R_ROWS, 1024, gB1, bB1, invR);
    convW_split<<<(1024 * 1024 + 255) / 256, 256>>>(WB2, bH, bL, 1024 * 1024);
    tc(pre, R_ROWS, 1024, 1024);
    stats_pass(pre, R_ROWS, 1024);
    bn_relu_max_T<<<BN_ROWS, 256>>>(pre, stats, gB2, bB2, out, 1024, invR);

    (void)in_sizes; (void)n_in; (void)out_size;
}